// round 15
// baseline (speedup 1.0000x reference)
#include <cuda_runtime.h>
#include <cuda_fp16.h>
#include <math.h>

typedef unsigned int u32;

// ---------------- problem constants ----------------
#define S_TOT 9616
#define RAZOR 8320
#define PF    1040
#define ROT   8576
#define NH    2
#define HD    128
#define PRE   2048
#define WIN   301
// SCALE * log2(e), absorbed into Q at prep; scores exponentiated with ex2
#define QSCALE 0.12751741522f
#define ONES16 0x3C003C00u     // fp16 {1.0, 1.0}

// rotated fp16 buffers [h][s][d]  (Q pre-scaled by QSCALE)
__device__ __half g_Qh[(size_t)NH*S_TOT*HD];
__device__ __half g_Kh[(size_t)NH*S_TOT*HD];
__device__ __half g_Vh[(size_t)NH*S_TOT*HD];

// tail-tile partial scratch: 11 tiles x 2 heads x 8 chunks
#define NCHUNK 8
__device__ float g_scrO[(size_t)11*2*NCHUNK*128*128];
__device__ float g_scrL[(size_t)11*2*NCHUNK*128];
__device__ int   g_cnt[22];          // per (tile,head) pair completion counters

__device__ __forceinline__ int orig_idx(int r) { return r < ROT ? r + PF : r - ROT; }

__device__ __forceinline__ u32 smem_u32(const void* p) {
    u32 a;
    asm("{ .reg .u64 t; cvta.to.shared.u64 t, %1; cvt.u32.u64 %0, t; }" : "=r"(a) : "l"(p));
    return a;
}
__device__ __forceinline__ void ldsm4(u32* r, u32 a) {
    asm volatile("ldmatrix.sync.aligned.m8n8.x4.shared.b16 {%0,%1,%2,%3}, [%4];"
                 : "=r"(r[0]), "=r"(r[1]), "=r"(r[2]), "=r"(r[3]) : "r"(a));
}
__device__ __forceinline__ void ldsm4t(u32* r, u32 a) {
    asm volatile("ldmatrix.sync.aligned.m8n8.x4.trans.shared.b16 {%0,%1,%2,%3}, [%4];"
                 : "=r"(r[0]), "=r"(r[1]), "=r"(r[2]), "=r"(r[3]) : "r"(a));
}
__device__ __forceinline__ void mma(float* d, const u32* a, u32 b0, u32 b1) {
    asm volatile("mma.sync.aligned.m16n8k16.row.col.f32.f16.f16.f32 "
                 "{%0,%1,%2,%3},{%4,%5,%6,%7},{%8,%9},{%0,%1,%2,%3};"
                 : "+f"(d[0]), "+f"(d[1]), "+f"(d[2]), "+f"(d[3])
                 : "r"(a[0]), "r"(a[1]), "r"(a[2]), "r"(a[3]), "r"(b0), "r"(b1));
}
__device__ __forceinline__ u32 pack2(float a, float b) {
    __half2 t = __floats2half2_rn(a, b);
    return *(u32*)&t;
}
__device__ __forceinline__ float ex2(float x) {
    float r;
    asm("ex2.approx.ftz.f32 %0, %1;" : "=f"(r) : "f"(x));
    return r;
}

#define CP_ASYNC16(d, s) asm volatile("cp.async.cg.shared.global [%0], [%1], 16;" :: "r"(d), "l"(s))
#define CP_COMMIT()      asm volatile("cp.async.commit_group;" ::: "memory")
#define CP_WAIT1()       asm volatile("cp.async.wait_group 1;" ::: "memory")

// ---------------- smem layout ----------------
#define RSTR 272
#define KROWS (128*RSTR)               // 34816: 128 rows (K or V)
#define KVBUF (2*KROWS)                // 69632: [KH(128r) | VH(128r)]
#define NSTG  3
#define SMEM_ATTN (NSTG*KVBUF)         // 208896

// ---------------- prep: rotate + fp16 convert + zero ratio & counters ----------------
__global__ __launch_bounds__(256) void prep_qkv(const float* __restrict__ Q,
                                                const float* __restrict__ K,
                                                const float* __restrict__ V,
                                                float* __restrict__ ratio) {
    if (blockIdx.x == 0 && blockIdx.y == 0) {
        if (threadIdx.x < 4) ratio[threadIdx.x] = 0.f;
        if (threadIdx.x >= 32 && threadIdx.x < 54) g_cnt[threadIdx.x - 32] = 0;
    }
    int h = blockIdx.y;
    int s = blockIdx.x * 8 + (threadIdx.x >> 5);
    if (s >= S_TOT) return;
    int lane = threadIdx.x & 31;
    int gq = orig_idx(s);
    size_t si = ((size_t)gq * NH + h) * HD + lane * 4;
    size_t o  = ((size_t)h * S_TOT + s) * HD + lane * 4;
    float4 qv = *(const float4*)(Q + si);
    float4 kv = *(const float4*)(K + si);
    float4 vv = *(const float4*)(V + si);
    *(uint2*)(g_Qh + o) = make_uint2(pack2(qv.x * QSCALE, qv.y * QSCALE),
                                     pack2(qv.z * QSCALE, qv.w * QSCALE));
    *(uint2*)(g_Kh + o) = make_uint2(pack2(kv.x, kv.y), pack2(kv.z, kv.w));
    *(uint2*)(g_Vh + o) = make_uint2(pack2(vv.x, vv.y), pack2(vv.z, vv.w));
}

// ---------------- async KV block load: 128 rows of K and V ----------------
__device__ __forceinline__ void kv_load(u32 kvb, int c0, int tid,
    const __half* kh, const __half* vh)
{
#pragma unroll
    for (int it = 0; it < 8; it++) {
        int idx = tid + it * 256;            // 0..2047
        int row = idx >> 4, ch = idx & 15;
        size_t src = (size_t)min(c0 + row, S_TOT - 1) * HD + ch * 8;
        u32 dst = kvb + row * RSTR + ch * 16;
        CP_ASYNC16(dst,         kh + src);
        CP_ASYNC16(dst + KROWS, vh + src);
    }
}

// ---------------- fused attention + ratio kernel ----------------
// grid order: razor 0..129, tail chunks 130..305, ratio 306..341 (backfill)
__global__ __launch_bounds__(256, 1)
void fused_kernel(float* __restrict__ O, float* __restrict__ ratio)
{
    extern __shared__ char sm[];
    const u32 sb  = smem_u32(sm);
    const int tid = threadIdx.x, w = tid >> 5, lane = tid & 31;
    const int g = lane >> 2, tg = lane & 3;

    if (blockIdx.x >= 306) {
        // ================= ratio path (fp16 QK, Q frags in registers) =================
        int e = blockIdx.x - 306;            // 0..35
        const int type = e / 18, head = (e / 9) & 1, rb = e % 9;
        const int r0 = rb * 128;
        const int stride = type ? 8 : 1;

        const __half* qh = g_Qh + (size_t)head * S_TOT * HD;
        const __half* kh = g_Kh + (size_t)head * S_TOT * HD;

        u32 qf[8][4];
        {
            const int rqa = min(r0 + w * 16 + g,     PF - 1) * stride;
            const int rqb = min(r0 + w * 16 + g + 8, PF - 1) * stride;
#pragma unroll
            for (int kc = 0; kc < 8; kc++) {
                int d = kc * 16 + 2 * tg;
                qf[kc][0] = *(const u32*)(qh + (size_t)rqa * HD + d);
                qf[kc][1] = *(const u32*)(qh + (size_t)rqb * HD + d);
                qf[kc][2] = *(const u32*)(qh + (size_t)rqa * HD + d + 8);
                qf[kc][3] = *(const u32*)(qh + (size_t)rqb * HD + d + 8);
            }
        }

        const u32 bAddr = sb + ((lane & 7) + ((lane >> 4) & 1) * 8) * RSTR
                        + ((lane >> 3) & 1) * 16;

        float totA = 0.f, winA = 0.f, totB = 0.f, winB = 0.f;
        const int rA = r0 + w * 16 + g, rB = rA + 8;

        for (int blk = 0; blk < 17; blk++) {
            const int c0 = blk * 64;
            __syncthreads();
#pragma unroll
            for (int it = 0; it < 4; it++) {
                int idx = tid + it * 256;
                int row = idx >> 4, ch = idx & 15;
                size_t src = (size_t)(min(c0 + row, PF - 1) * stride) * HD + ch * 8;
                *(uint4*)(sm + row * RSTR + ch * 16) = *(const uint4*)(kh + src);
            }
            __syncthreads();

            float s[8][4];
#pragma unroll
            for (int x = 0; x < 8; x++)
#pragma unroll
                for (int j = 0; j < 4; j++) s[x][j] = 0.f;
#pragma unroll
            for (int kc = 0; kc < 8; kc++) {
#pragma unroll
                for (int nb2 = 0; nb2 < 4; nb2++) {
                    u32 Bh[4];
                    ldsm4(Bh, bAddr + nb2 * (16 * RSTR) + kc * 32);
                    mma(s[2*nb2],   qf[kc], Bh[0], Bh[1]);
                    mma(s[2*nb2+1], qf[kc], Bh[2], Bh[3]);
                }
            }
#pragma unroll
            for (int nb = 0; nb < 8; nb++) {
                int c = c0 + nb * 8 + 2 * tg;
#pragma unroll
                for (int v = 0; v < 4; v++) {
                    int cc = c + (v & 1);
                    int rr = (v < 2) ? rA : rB;
                    float p = (cc < PF) ? ex2(s[nb][v]) : 0.f;
                    if (v < 2) { totA += p; if (abs(rr - cc) <= WIN) winA += p; }
                    else       { totB += p; if (abs(rr - cc) <= WIN) winB += p; }
                }
            }
        }

        totA += __shfl_xor_sync(0xffffffffu, totA, 1);
        totA += __shfl_xor_sync(0xffffffffu, totA, 2);
        winA += __shfl_xor_sync(0xffffffffu, winA, 1);
        winA += __shfl_xor_sync(0xffffffffu, winA, 2);
        totB += __shfl_xor_sync(0xffffffffu, totB, 1);
        totB += __shfl_xor_sync(0xffffffffu, totB, 2);
        winB += __shfl_xor_sync(0xffffffffu, winB, 1);
        winB += __shfl_xor_sync(0xffffffffu, winB, 2);

        float* red = (float*)sm;
        __syncthreads();
        if (tid == 0) red[0] = 0.f;
        __syncthreads();
        if (tg == 0) {
            float contrib = 0.f;
            if (rA < PF) contrib += winA / totA;
            if (rB < PF) contrib += winB / totB;
            if (contrib != 0.f) atomicAdd(red, contrib);
        }
        __syncthreads();
        if (tid == 0) atomicAdd(&ratio[type * NH + head], red[0] * (1.f / (float)PF));
        return;
    }

    // ================= attention path (128-col big-iters, 3-stage pipeline) =================
    int tile, head, chunk = -1, eidx = 0;
    int lo0, hi0, lo1, hi1;
    if (blockIdx.x < 130) {
        tile = blockIdx.x >> 1; head = blockIdx.x & 1;
        lo0 = max(0, tile - 16); hi0 = min(64, tile + 16);   // band, 128-blocks
        lo1 = 65; hi1 = 75;                                   // tail
    } else {
        int e = blockIdx.x - 130;
        int tileIdx = e >> 4; head = (e >> 3) & 1; chunk = e & 7;
        tile = 65 + tileIdx;
        eidx = e;
        lo0 = (76 * chunk) / 8; hi0 = (76 * (chunk + 1)) / 8 - 1;
        lo1 = 0; hi1 = -1;
    }
    const int r0 = tile * 128;
    const bool rowRazor = (tile < 65);
    const int n0 = hi0 - lo0 + 1;
    const int nb_total = n0 + (hi1 >= lo1 ? hi1 - lo1 + 1 : 0);

    const __half* qh = g_Qh + (size_t)head * S_TOT * HD;
    const __half* kh = g_Kh + (size_t)head * S_TOT * HD;
    const __half* vh = g_Vh + (size_t)head * S_TOT * HD;

#define BLK_OF(j) (((j) < n0) ? lo0 + (j) : lo1 + ((j) - n0))

    // prologue: issue loads for big-iters 0 and 1
    kv_load(sb,         BLK_OF(0) * 128, tid, kh, vh);
    CP_COMMIT();
    kv_load(sb + KVBUF, BLK_OF(min(1, nb_total - 1)) * 128, tid, kh, vh);
    CP_COMMIT();

    // Q fragments direct from global (A-frag layout), held for entire kernel
    u32 qf[8][4];
    {
        const int rqa = min(r0 + w * 16 + g,     S_TOT - 1);
        const int rqb = min(r0 + w * 16 + g + 8, S_TOT - 1);
#pragma unroll
        for (int kc = 0; kc < 8; kc++) {
            int d = kc * 16 + 2 * tg;
            qf[kc][0] = *(const u32*)(qh + (size_t)rqa * HD + d);
            qf[kc][1] = *(const u32*)(qh + (size_t)rqb * HD + d);
            qf[kc][2] = *(const u32*)(qh + (size_t)rqa * HD + d + 8);
            qf[kc][3] = *(const u32*)(qh + (size_t)rqb * HD + d + 8);
        }
    }

    const u32 offBK = ((lane & 7) + ((lane >> 4) & 1) * 8) * RSTR + ((lane >> 3) & 1) * 16;
    const u32 offBV = KROWS + ((lane & 7) + ((lane >> 3) & 1) * 8) * RSTR + ((lane >> 4) & 1) * 16;

    float o[16][4];
#pragma unroll
    for (int i = 0; i < 16; i++)
#pragma unroll
        for (int j = 0; j < 4; j++) o[i][j] = 0.f;
    float laccF[4] = {0.f, 0.f, 0.f, 0.f};      // row sums via ones-MMA
    const int rA = r0 + w * 16 + g, rB = rA + 8;
    const int t2lo = 2 * tile - 30, t2hi = 2 * tile + 31;

    int st = 0;
    for (int i = 0; i < nb_total; i++) {
        const int blk = BLK_OF(i);

        CP_WAIT1();
        __syncthreads();
        {
            int nxt = i + 2;
            if (nxt < nb_total) {
                int ns = st + 2; if (ns >= NSTG) ns -= NSTG;
                kv_load(sb + ns * KVBUF, BLK_OF(nxt) * 128, tid, kh, vh);
            }
            CP_COMMIT();
        }
        const u32 kvb = sb + st * KVBUF;
        if (++st == NSTG) st = 0;

#pragma unroll
        for (int h = 0; h < 2; h++) {
            const int sub = 2 * blk + h;
            if (sub == 151) continue;
            const int c0 = sub * 64;
            int maskMode = 0;
            if (sub < 130) { if (rowRazor && (sub < t2lo || sub > t2hi)) maskMode = 1; }
            else if (sub == 150) maskMode = 2;
            const u32 hof = h * (64 * RSTR);

            // ---- QK: S = Qh * Kh ----
            float s[8][4];
#pragma unroll
            for (int x = 0; x < 8; x++)
#pragma unroll
                for (int j = 0; j < 4; j++) s[x][j] = 0.f;

#pragma unroll
            for (int kc = 0; kc < 8; kc++) {
#pragma unroll
                for (int nb2 = 0; nb2 < 4; nb2++) {
                    u32 Bh[4];
                    ldsm4(Bh, kvb + offBK + hof + nb2 * (16 * RSTR) + kc * 32);
                    mma(s[2*nb2],   qf[kc], Bh[0], Bh[1]);
                    mma(s[2*nb2+1], qf[kc], Bh[2], Bh[3]);
                }
            }

            // ---- epilogue: mask + ex2 + fp16 pack ----
            u32 ph[8][2];
#pragma unroll
            for (int nb = 0; nb < 8; nb++) {
                int c = c0 + nb * 8 + 2 * tg;
                float p00 = ex2(s[nb][0]);
                float p01 = ex2(s[nb][1]);
                float p10 = ex2(s[nb][2]);
                float p11 = ex2(s[nb][3]);
                if (maskMode == 1) {
                    if ((unsigned)(c     - (rA - PRE)) > 2u*PRE) p00 = 0.f;
                    if ((unsigned)(c + 1 - (rA - PRE)) > 2u*PRE) p01 = 0.f;
                    if ((unsigned)(c     - (rB - PRE)) > 2u*PRE) p10 = 0.f;
                    if ((unsigned)(c + 1 - (rB - PRE)) > 2u*PRE) p11 = 0.f;
                } else if (maskMode == 2) {
                    if (c     >= S_TOT) { p00 = 0.f; p10 = 0.f; }
                    if (c + 1 >= S_TOT) { p01 = 0.f; p11 = 0.f; }
                }
                ph[nb][0] = pack2(p00, p01);
                ph[nb][1] = pack2(p10, p11);
            }

            // ---- PV: O += P * Vh ; lacc += P * ones ----
#pragma unroll
            for (int kc = 0; kc < 4; kc++) {
                u32 Ah[4] = { ph[2*kc][0], ph[2*kc][1], ph[2*kc+1][0], ph[2*kc+1][1] };
                mma(laccF, Ah, ONES16, ONES16);
#pragma unroll
                for (int nb2 = 0; nb2 < 8; nb2++) {
                    u32 Bh[4];
                    ldsm4t(Bh, kvb + offBV + hof + kc * (16 * RSTR) + nb2 * 32);
                    mma(o[2*nb2],   Ah, Bh[0], Bh[1]);
                    mma(o[2*nb2+1], Ah, Bh[2], Bh[3]);
                }
            }
        }
    }

    // ---- finalize ----
    const float laccA = laccF[0], laccB = laccF[2];

    if (chunk < 0) {
        float invA = 1.f / laccA, invB = 1.f / laccB;
        if (rA < S_TOT) {
            float* base = O + ((size_t)orig_idx(rA) * NH + head) * HD;
#pragma unroll
            for (int nb = 0; nb < 16; nb++)
                *(float2*)(base + nb * 8 + 2 * tg) = make_float2(o[nb][0] * invA, o[nb][1] * invA);
        }
        if (rB < S_TOT) {
            float* base = O + ((size_t)orig_idx(rB) * NH + head) * HD;
#pragma unroll
            for (int nb = 0; nb < 16; nb++)
                *(float2*)(base + nb * 8 + 2 * tg) = make_float2(o[nb][2] * invB, o[nb][3] * invB);
        }
    } else {
        // ---- tail chunk: write unnormalized partials, last arriver combines ----
        float* so = g_scrO + (size_t)eidx * 16384;
        int rlA = w * 16 + g, rlB = rlA + 8;
#pragma unroll
        for (int nb = 0; nb < 16; nb++) {
            *(float2*)(so + rlA * 128 + nb * 8 + 2 * tg) = make_float2(o[nb][0], o[nb][1]);
            *(float2*)(so + rlB * 128 + nb * 8 + 2 * tg) = make_float2(o[nb][2], o[nb][3]);
        }
        if (tg == 0) {
            g_scrL[eidx * 128 + rlA] = laccA;
            g_scrL[eidx * 128 + rlB] = laccB;
        }
        __syncthreads();
        __threadfence();
        int* flag = (int*)sm;
        if (tid == 0) {
            int pairIdx = (tile - 65) * 2 + head;          // 0..21
            flag[0] = (atomicAdd(&g_cnt[pairIdx], 1) == NCHUNK - 1);
        }
        __syncthreads();
        if (flag[0]) {
            // this CTA is last for its (tile, head) pair: combine 8 chunks
            const int tileIdx = tile - 65;
            const int ebase = tileIdx * 16 + head * 8;
            float* ls = (float*)(sm + 64);
            if (tid < 128) {
                float sum = 0.f;
#pragma unroll
                for (int c = 0; c < NCHUNK; c++) sum += g_scrL[(ebase + c) * 128 + tid];
                ls[tid] = 1.f / sum;
            }
            __syncthreads();
            for (int k = tid; k < 16384; k += 256) {
                int row = k >> 7, col = k & 127;
                if (r0 + row >= S_TOT) continue;
                float sum = 0.f;
#pragma unroll
                for (int c = 0; c < NCHUNK; c++)
                    sum += g_scrO[(size_t)(ebase + c) * 16384 + k];
                int gr = orig_idx(r0 + row);
                O[((size_t)gr * NH + head) * HD + col] = sum * ls[row];
            }
        }
    }
}

// ---------------- launch ----------------
extern "C" void kernel_launch(void* const* d_in, const int* in_sizes, int n_in,
                              void* d_out, int out_size)
{
    const float* Q = (const float*)d_in[0];
    const float* K = (const float*)d_in[1];
    const float* V = (const float*)d_in[2];
    float* O     = (float*)d_out;
    float* ratio = O + (size_t)S_TOT * NH * HD;

    cudaFuncSetAttribute(fused_kernel, cudaFuncAttributeMaxDynamicSharedMemorySize, SMEM_ATTN);

    prep_qkv<<<dim3(1202, NH), 256>>>(Q, K, V, ratio);
    fused_kernel<<<342, 256, SMEM_ATTN>>>(O, ratio);
}

// round 16
// speedup vs baseline: 1.1073x; 1.1073x over previous
#include <cuda_runtime.h>
#include <cuda_fp16.h>
#include <math.h>

typedef unsigned int u32;

// ---------------- problem constants ----------------
#define S_TOT 9616
#define RAZOR 8320
#define PF    1040
#define ROT   8576
#define NH    2
#define HD    128
#define PRE   2048
#define WIN   301
// SCALE * log2(e), absorbed into Q at prep; scores exponentiated with ex2
#define QSCALE 0.12751741522f
#define ONES16 0x3C003C00u     // fp16 {1.0, 1.0}

// rotated fp16 buffers [h][s][d]  (Q pre-scaled by QSCALE)
__device__ __half g_Qh[(size_t)NH*S_TOT*HD];
__device__ __half g_Kh[(size_t)NH*S_TOT*HD];
__device__ __half g_Vh[(size_t)NH*S_TOT*HD];

// tail-tile partial scratch: 11 tiles x 2 heads x 8 chunks
#define NCHUNK 8
__device__ float g_scrO[(size_t)11*2*NCHUNK*128*128];
__device__ float g_scrL[(size_t)11*2*NCHUNK*128];

__device__ __forceinline__ int orig_idx(int r) { return r < ROT ? r + PF : r - ROT; }

__device__ __forceinline__ u32 smem_u32(const void* p) {
    u32 a;
    asm("{ .reg .u64 t; cvta.to.shared.u64 t, %1; cvt.u32.u64 %0, t; }" : "=r"(a) : "l"(p));
    return a;
}
__device__ __forceinline__ void ldsm4(u32* r, u32 a) {
    asm volatile("ldmatrix.sync.aligned.m8n8.x4.shared.b16 {%0,%1,%2,%3}, [%4];"
                 : "=r"(r[0]), "=r"(r[1]), "=r"(r[2]), "=r"(r[3]) : "r"(a));
}
__device__ __forceinline__ void ldsm4t(u32* r, u32 a) {
    asm volatile("ldmatrix.sync.aligned.m8n8.x4.trans.shared.b16 {%0,%1,%2,%3}, [%4];"
                 : "=r"(r[0]), "=r"(r[1]), "=r"(r[2]), "=r"(r[3]) : "r"(a));
}
__device__ __forceinline__ void mma(float* d, const u32* a, u32 b0, u32 b1) {
    asm volatile("mma.sync.aligned.m16n8k16.row.col.f32.f16.f16.f32 "
                 "{%0,%1,%2,%3},{%4,%5,%6,%7},{%8,%9},{%0,%1,%2,%3};"
                 : "+f"(d[0]), "+f"(d[1]), "+f"(d[2]), "+f"(d[3])
                 : "r"(a[0]), "r"(a[1]), "r"(a[2]), "r"(a[3]), "r"(b0), "r"(b1));
}
__device__ __forceinline__ u32 pack2(float a, float b) {
    __half2 t = __floats2half2_rn(a, b);
    return *(u32*)&t;
}
__device__ __forceinline__ float ex2(float x) {
    float r;
    asm("ex2.approx.ftz.f32 %0, %1;" : "=f"(r) : "f"(x));
    return r;
}

#define CP_ASYNC16(d, s) asm volatile("cp.async.cg.shared.global [%0], [%1], 16;" :: "r"(d), "l"(s))
#define CP_COMMIT()      asm volatile("cp.async.commit_group;" ::: "memory")
#define CP_WAIT1()       asm volatile("cp.async.wait_group 1;" ::: "memory")

// ---------------- smem layout ----------------
#define RSTR 272
#define KROWS (128*RSTR)               // 34816: 128 rows (K or V)
#define KVBUF (2*KROWS)                // 69632: [KH(128r) | VH(128r)]
#define NSTG  3
#define SMEM_ATTN (NSTG*KVBUF)         // 208896

// ---------------- prep: rotate + fp16 convert (Q pre-scaled) + zero ratio ----------------
__global__ __launch_bounds__(256) void prep_qkv(const float* __restrict__ Q,
                                                const float* __restrict__ K,
                                                const float* __restrict__ V,
                                                float* __restrict__ ratio) {
    if (blockIdx.x == 0 && blockIdx.y == 0 && threadIdx.x < 4) ratio[threadIdx.x] = 0.f;
    int h = blockIdx.y;
    int s = blockIdx.x * 8 + (threadIdx.x >> 5);
    if (s >= S_TOT) return;
    int lane = threadIdx.x & 31;
    int gq = orig_idx(s);
    size_t si = ((size_t)gq * NH + h) * HD + lane * 4;
    size_t o  = ((size_t)h * S_TOT + s) * HD + lane * 4;
    float4 qv = *(const float4*)(Q + si);
    float4 kv = *(const float4*)(K + si);
    float4 vv = *(const float4*)(V + si);
    *(uint2*)(g_Qh + o) = make_uint2(pack2(qv.x * QSCALE, qv.y * QSCALE),
                                     pack2(qv.z * QSCALE, qv.w * QSCALE));
    *(uint2*)(g_Kh + o) = make_uint2(pack2(kv.x, kv.y), pack2(kv.z, kv.w));
    *(uint2*)(g_Vh + o) = make_uint2(pack2(vv.x, vv.y), pack2(vv.z, vv.w));
}

// ---------------- async KV block load: 128 rows of K and V ----------------
__device__ __forceinline__ void kv_load(u32 kvb, int c0, int tid,
    const __half* kh, const __half* vh)
{
#pragma unroll
    for (int it = 0; it < 8; it++) {
        int idx = tid + it * 256;            // 0..2047
        int row = idx >> 4, ch = idx & 15;
        size_t src = (size_t)min(c0 + row, S_TOT - 1) * HD + ch * 8;
        u32 dst = kvb + row * RSTR + ch * 16;
        CP_ASYNC16(dst,         kh + src);
        CP_ASYNC16(dst + KROWS, vh + src);
    }
}

// ---------------- fused attention + ratio kernel (exact R12 structure) ----------------
__global__ __launch_bounds__(256, 1)
void fused_kernel(float* __restrict__ O, float* __restrict__ ratio)
{
    extern __shared__ char sm[];
    const u32 sb  = smem_u32(sm);
    const int tid = threadIdx.x, w = tid >> 5, lane = tid & 31;
    const int g = lane >> 2, tg = lane & 3;

    if (blockIdx.x >= 306) {
        // ================= ratio path (fp16 QK, Q frags in registers) =================
        int e = blockIdx.x - 306;            // 0..35
        const int type = e / 18, head = (e / 9) & 1, rb = e % 9;
        const int r0 = rb * 128;
        const int stride = type ? 8 : 1;

        const __half* qh = g_Qh + (size_t)head * S_TOT * HD;
        const __half* kh = g_Kh + (size_t)head * S_TOT * HD;

        // Q fragments direct from global (A-frag layout)
        u32 qf[8][4];
        {
            const int rqa = min(r0 + w * 16 + g,     PF - 1) * stride;
            const int rqb = min(r0 + w * 16 + g + 8, PF - 1) * stride;
#pragma unroll
            for (int kc = 0; kc < 8; kc++) {
                int d = kc * 16 + 2 * tg;
                qf[kc][0] = *(const u32*)(qh + (size_t)rqa * HD + d);
                qf[kc][1] = *(const u32*)(qh + (size_t)rqb * HD + d);
                qf[kc][2] = *(const u32*)(qh + (size_t)rqa * HD + d + 8);
                qf[kc][3] = *(const u32*)(qh + (size_t)rqb * HD + d + 8);
            }
        }

        const u32 bAddr = sb + ((lane & 7) + ((lane >> 4) & 1) * 8) * RSTR
                        + ((lane >> 3) & 1) * 16;

        float totA = 0.f, winA = 0.f, totB = 0.f, winB = 0.f;
        const int rA = r0 + w * 16 + g, rB = rA + 8;

        for (int blk = 0; blk < 17; blk++) {
            const int c0 = blk * 64;
            __syncthreads();
#pragma unroll
            for (int it = 0; it < 4; it++) {
                int idx = tid + it * 256;
                int row = idx >> 4, ch = idx & 15;
                size_t src = (size_t)(min(c0 + row, PF - 1) * stride) * HD + ch * 8;
                *(uint4*)(sm + row * RSTR + ch * 16) = *(const uint4*)(kh + src);
            }
            __syncthreads();

            float s[8][4];
#pragma unroll
            for (int x = 0; x < 8; x++)
#pragma unroll
                for (int j = 0; j < 4; j++) s[x][j] = 0.f;
#pragma unroll
            for (int kc = 0; kc < 8; kc++) {
#pragma unroll
                for (int nb2 = 0; nb2 < 4; nb2++) {
                    u32 Bh[4];
                    ldsm4(Bh, bAddr + nb2 * (16 * RSTR) + kc * 32);
                    mma(s[2*nb2],   qf[kc], Bh[0], Bh[1]);
                    mma(s[2*nb2+1], qf[kc], Bh[2], Bh[3]);
                }
            }
#pragma unroll
            for (int nb = 0; nb < 8; nb++) {
                int c = c0 + nb * 8 + 2 * tg;
#pragma unroll
                for (int v = 0; v < 4; v++) {
                    int cc = c + (v & 1);
                    int rr = (v < 2) ? rA : rB;
                    float p = (cc < PF) ? ex2(s[nb][v]) : 0.f;
                    if (v < 2) { totA += p; if (abs(rr - cc) <= WIN) winA += p; }
                    else       { totB += p; if (abs(rr - cc) <= WIN) winB += p; }
                }
            }
        }

        totA += __shfl_xor_sync(0xffffffffu, totA, 1);
        totA += __shfl_xor_sync(0xffffffffu, totA, 2);
        winA += __shfl_xor_sync(0xffffffffu, winA, 1);
        winA += __shfl_xor_sync(0xffffffffu, winA, 2);
        totB += __shfl_xor_sync(0xffffffffu, totB, 1);
        totB += __shfl_xor_sync(0xffffffffu, totB, 2);
        winB += __shfl_xor_sync(0xffffffffu, winB, 1);
        winB += __shfl_xor_sync(0xffffffffu, winB, 2);

        float* red = (float*)sm;
        __syncthreads();
        if (tid == 0) red[0] = 0.f;
        __syncthreads();
        if (tg == 0) {
            float contrib = 0.f;
            if (rA < PF) contrib += winA / totA;
            if (rB < PF) contrib += winB / totB;
            if (contrib != 0.f) atomicAdd(red, contrib);
        }
        __syncthreads();
        if (tid == 0) atomicAdd(&ratio[type * NH + head], red[0] * (1.f / (float)PF));
        return;
    }

    // ================= attention path (128-col big-iters, 3-stage pipeline) =================
    int tile, head, chunk = -1, eidx = 0;
    int lo0, hi0, lo1, hi1;
    if (blockIdx.x < 130) {
        tile = blockIdx.x >> 1; head = blockIdx.x & 1;
        lo0 = max(0, tile - 16); hi0 = min(64, tile + 16);   // band, 128-blocks
        lo1 = 65; hi1 = 75;                                   // tail
    } else {
        int e = blockIdx.x - 130;
        int tileIdx = e >> 4; head = (e >> 3) & 1; chunk = e & 7;
        tile = 65 + tileIdx;
        eidx = e;
        lo0 = (76 * chunk) / 8; hi0 = (76 * (chunk + 1)) / 8 - 1;
        lo1 = 0; hi1 = -1;
    }
    const int r0 = tile * 128;
    const bool rowRazor = (tile < 65);
    const int n0 = hi0 - lo0 + 1;
    const int nb_total = n0 + (hi1 >= lo1 ? hi1 - lo1 + 1 : 0);

    const __half* qh = g_Qh + (size_t)head * S_TOT * HD;
    const __half* kh = g_Kh + (size_t)head * S_TOT * HD;
    const __half* vh = g_Vh + (size_t)head * S_TOT * HD;

#define BLK_OF(j) (((j) < n0) ? lo0 + (j) : lo1 + ((j) - n0))

    // prologue: issue loads for big-iters 0 and 1
    kv_load(sb,         BLK_OF(0) * 128, tid, kh, vh);
    CP_COMMIT();
    kv_load(sb + KVBUF, BLK_OF(min(1, nb_total - 1)) * 128, tid, kh, vh);
    CP_COMMIT();

    // Q fragments direct from global (A-frag layout), held for entire kernel
    u32 qf[8][4];
    {
        const int rqa = min(r0 + w * 16 + g,     S_TOT - 1);
        const int rqb = min(r0 + w * 16 + g + 8, S_TOT - 1);
#pragma unroll
        for (int kc = 0; kc < 8; kc++) {
            int d = kc * 16 + 2 * tg;
            qf[kc][0] = *(const u32*)(qh + (size_t)rqa * HD + d);
            qf[kc][1] = *(const u32*)(qh + (size_t)rqb * HD + d);
            qf[kc][2] = *(const u32*)(qh + (size_t)rqa * HD + d + 8);
            qf[kc][3] = *(const u32*)(qh + (size_t)rqb * HD + d + 8);
        }
    }

    const u32 offBK = ((lane & 7) + ((lane >> 4) & 1) * 8) * RSTR + ((lane >> 3) & 1) * 16;
    const u32 offBV = KROWS + ((lane & 7) + ((lane >> 3) & 1) * 8) * RSTR + ((lane >> 4) & 1) * 16;

    float o[16][4];
#pragma unroll
    for (int i = 0; i < 16; i++)
#pragma unroll
        for (int j = 0; j < 4; j++) o[i][j] = 0.f;
    float laccF[4] = {0.f, 0.f, 0.f, 0.f};      // row sums via ones-MMA
    const int rA = r0 + w * 16 + g, rB = rA + 8;
    const int t2lo = 2 * tile - 30, t2hi = 2 * tile + 31;

    int st = 0;                                   // stage being consumed
    for (int i = 0; i < nb_total; i++) {
        const int blk = BLK_OF(i);

        CP_WAIT1();            // iter i's group complete (<=1 outstanding)
        __syncthreads();       // CTA-wide visibility; all warps past iter i-1
        {
            int nxt = i + 2;
            if (nxt < nb_total) {
                int ns = st + 2; if (ns >= NSTG) ns -= NSTG;   // stage freed at i-1
                kv_load(sb + ns * KVBUF, BLK_OF(nxt) * 128, tid, kh, vh);
            }
            CP_COMMIT();       // uniform group counting
        }
        const u32 kvb = sb + st * KVBUF;
        if (++st == NSTG) st = 0;

#pragma unroll
        for (int h = 0; h < 2; h++) {
            const int sub = 2 * blk + h;          // 64-col sub-block index
            if (sub == 151) continue;             // beyond sequence entirely
            const int c0 = sub * 64;
            int maskMode = 0;
            if (sub < 130) { if (rowRazor && (sub < t2lo || sub > t2hi)) maskMode = 1; }
            else if (sub == 150) maskMode = 2;
            const u32 hof = h * (64 * RSTR);

            // ---- QK: S = Qh * Kh ----
            float s[8][4];
#pragma unroll
            for (int x = 0; x < 8; x++)
#pragma unroll
                for (int j = 0; j < 4; j++) s[x][j] = 0.f;

#pragma unroll
            for (int kc = 0; kc < 8; kc++) {
#pragma unroll
                for (int nb2 = 0; nb2 < 4; nb2++) {
                    u32 Bh[4];
                    ldsm4(Bh, kvb + offBK + hof + nb2 * (16 * RSTR) + kc * 32);
                    mma(s[2*nb2],   qf[kc], Bh[0], Bh[1]);
                    mma(s[2*nb2+1], qf[kc], Bh[2], Bh[3]);
                }
            }

            // ---- epilogue: mask + ex2 + fp16 pack ----
            u32 ph[8][2];
#pragma unroll
            for (int nb = 0; nb < 8; nb++) {
                int c = c0 + nb * 8 + 2 * tg;
                float p00 = ex2(s[nb][0]);
                float p01 = ex2(s[nb][1]);
                float p10 = ex2(s[nb][2]);
                float p11 = ex2(s[nb][3]);
                if (maskMode == 1) {
                    if ((unsigned)(c     - (rA - PRE)) > 2u*PRE) p00 = 0.f;
                    if ((unsigned)(c + 1 - (rA - PRE)) > 2u*PRE) p01 = 0.f;
                    if ((unsigned)(c     - (rB - PRE)) > 2u*PRE) p10 = 0.f;
                    if ((unsigned)(c + 1 - (rB - PRE)) > 2u*PRE) p11 = 0.f;
                } else if (maskMode == 2) {
                    if (c     >= S_TOT) { p00 = 0.f; p10 = 0.f; }
                    if (c + 1 >= S_TOT) { p01 = 0.f; p11 = 0.f; }
                }
                ph[nb][0] = pack2(p00, p01);
                ph[nb][1] = pack2(p10, p11);
            }

            // ---- PV: O += P * Vh ; lacc += P * ones ----
#pragma unroll
            for (int kc = 0; kc < 4; kc++) {
                u32 Ah[4] = { ph[2*kc][0], ph[2*kc][1], ph[2*kc+1][0], ph[2*kc+1][1] };
                mma(laccF, Ah, ONES16, ONES16);     // row sums (free l accumulation)
#pragma unroll
                for (int nb2 = 0; nb2 < 8; nb2++) {
                    u32 Bh[4];
                    ldsm4t(Bh, kvb + offBV + hof + kc * (16 * RSTR) + nb2 * 32);
                    mma(o[2*nb2],   Ah, Bh[0], Bh[1]);
                    mma(o[2*nb2+1], Ah, Bh[2], Bh[3]);
                }
            }
        }
    }

    // ---- finalize (laccF[0]/[2] are complete row sums) ----
    const float laccA = laccF[0], laccB = laccF[2];

    if (chunk < 0) {
        float invA = 1.f / laccA, invB = 1.f / laccB;
        if (rA < S_TOT) {
            float* base = O + ((size_t)orig_idx(rA) * NH + head) * HD;
#pragma unroll
            for (int nb = 0; nb < 16; nb++)
                *(float2*)(base + nb * 8 + 2 * tg) = make_float2(o[nb][0] * invA, o[nb][1] * invA);
        }
        if (rB < S_TOT) {
            float* base = O + ((size_t)orig_idx(rB) * NH + head) * HD;
#pragma unroll
            for (int nb = 0; nb < 16; nb++)
                *(float2*)(base + nb * 8 + 2 * tg) = make_float2(o[nb][2] * invB, o[nb][3] * invB);
        }
    } else {
        float* so = g_scrO + (size_t)eidx * 16384;
        int rlA = w * 16 + g, rlB = rlA + 8;
#pragma unroll
        for (int nb = 0; nb < 16; nb++) {
            *(float2*)(so + rlA * 128 + nb * 8 + 2 * tg) = make_float2(o[nb][0], o[nb][1]);
            *(float2*)(so + rlB * 128 + nb * 8 + 2 * tg) = make_float2(o[nb][2], o[nb][3]);
        }
        if (tg == 0) {
            g_scrL[eidx * 128 + rlA] = laccA;
            g_scrL[eidx * 128 + rlB] = laccB;
        }
    }
}

// ---------------- combine tail partials (wide grid, float4) ----------------
// grid 352 = 22 pairs x 16 slices; each block: 1024 elems = 1 float4/thread/chunk
__global__ __launch_bounds__(256) void combine_kernel(float* __restrict__ O) {
    int pair  = blockIdx.x >> 4;
    int slice = blockIdx.x & 15;
    int tileIdx = pair >> 1, head = pair & 1;
    int tile = 65 + tileIdx, r0 = tile * 128;
    int ebase = tileIdx * 16 + head * 8;
    int tid = threadIdx.x;

    __shared__ float ls[8];
    if (tid < 8) {
        int row = slice * 8 + tid;
        float sum = 0.f;
#pragma unroll
        for (int c = 0; c < NCHUNK; c++) sum += g_scrL[(ebase + c) * 128 + row];
        ls[tid] = 1.f / sum;
    }
    __syncthreads();

    int k = slice * 1024 + tid * 4;           // float4-aligned element index
    int row = k >> 7, col = k & 127;
    if (r0 + row >= S_TOT) return;
    float4 acc = make_float4(0.f, 0.f, 0.f, 0.f);
#pragma unroll
    for (int c = 0; c < NCHUNK; c++) {
        float4 v = *(const float4*)(g_scrO + (size_t)(ebase + c) * 16384 + k);
        acc.x += v.x; acc.y += v.y; acc.z += v.z; acc.w += v.w;
    }
    float inv = ls[row - slice * 8];
    int gr = orig_idx(r0 + row);
    acc.x *= inv; acc.y *= inv; acc.z *= inv; acc.w *= inv;
    *(float4*)(O + ((size_t)gr * NH + head) * HD + col) = acc;
}

// ---------------- launch ----------------
extern "C" void kernel_launch(void* const* d_in, const int* in_sizes, int n_in,
                              void* d_out, int out_size)
{
    const float* Q = (const float*)d_in[0];
    const float* K = (const float*)d_in[1];
    const float* V = (const float*)d_in[2];
    float* O     = (float*)d_out;
    float* ratio = O + (size_t)S_TOT * NH * HD;

    cudaFuncSetAttribute(fused_kernel, cudaFuncAttributeMaxDynamicSharedMemorySize, SMEM_ATTN);

    prep_qkv<<<dim3(1202, NH), 256>>>(Q, K, V, ratio);
    fused_kernel<<<342, 256, SMEM_ATTN>>>(O, ratio);
    combine_kernel<<<352, 256>>>(O);
}

// round 17
// speedup vs baseline: 1.1115x; 1.0037x over previous
#include <cuda_runtime.h>
#include <cuda_fp16.h>
#include <math.h>

typedef unsigned int u32;

// ---------------- problem constants ----------------
#define S_TOT 9616
#define RAZOR 8320
#define PF    1040
#define ROT   8576
#define NH    2
#define HD    128
#define PRE   2048
#define WIN   301
// SCALE * log2(e), absorbed into Q at prep; scores exponentiated with ex2
#define QSCALE 0.12751741522f
#define ONES16 0x3C003C00u     // fp16 {1.0, 1.0}

// rotated fp16 buffers [h][s][d]  (Q pre-scaled by QSCALE)
__device__ __half g_Qh[(size_t)NH*S_TOT*HD];
__device__ __half g_Kh[(size_t)NH*S_TOT*HD];
__device__ __half g_Vh[(size_t)NH*S_TOT*HD];

// tail-tile partial scratch: 11 tiles x 2 heads x 8 chunks
#define NCHUNK 8
__device__ float g_scrO[(size_t)11*2*NCHUNK*128*128];
__device__ float g_scrL[(size_t)11*2*NCHUNK*128];

__device__ __forceinline__ int orig_idx(int r) { return r < ROT ? r + PF : r - ROT; }

__device__ __forceinline__ u32 smem_u32(const void* p) {
    u32 a;
    asm("{ .reg .u64 t; cvta.to.shared.u64 t, %1; cvt.u32.u64 %0, t; }" : "=r"(a) : "l"(p));
    return a;
}
__device__ __forceinline__ void ldsm4(u32* r, u32 a) {
    asm volatile("ldmatrix.sync.aligned.m8n8.x4.shared.b16 {%0,%1,%2,%3}, [%4];"
                 : "=r"(r[0]), "=r"(r[1]), "=r"(r[2]), "=r"(r[3]) : "r"(a));
}
__device__ __forceinline__ void ldsm4t(u32* r, u32 a) {
    asm volatile("ldmatrix.sync.aligned.m8n8.x4.trans.shared.b16 {%0,%1,%2,%3}, [%4];"
                 : "=r"(r[0]), "=r"(r[1]), "=r"(r[2]), "=r"(r[3]) : "r"(a));
}
__device__ __forceinline__ void mma(float* d, const u32* a, u32 b0, u32 b1) {
    asm volatile("mma.sync.aligned.m16n8k16.row.col.f32.f16.f16.f32 "
                 "{%0,%1,%2,%3},{%4,%5,%6,%7},{%8,%9},{%0,%1,%2,%3};"
                 : "+f"(d[0]), "+f"(d[1]), "+f"(d[2]), "+f"(d[3])
                 : "r"(a[0]), "r"(a[1]), "r"(a[2]), "r"(a[3]), "r"(b0), "r"(b1));
}
__device__ __forceinline__ u32 pack2(float a, float b) {
    __half2 t = __floats2half2_rn(a, b);
    return *(u32*)&t;
}
__device__ __forceinline__ float ex2(float x) {
    float r;
    asm("ex2.approx.ftz.f32 %0, %1;" : "=f"(r) : "f"(x));
    return r;
}

#define CP_ASYNC16(d, s) asm volatile("cp.async.cg.shared.global [%0], [%1], 16;" :: "r"(d), "l"(s))
#define CP_COMMIT()      asm volatile("cp.async.commit_group;" ::: "memory")
#define CP_WAIT1()       asm volatile("cp.async.wait_group 1;" ::: "memory")

// ---------------- smem layout ----------------
#define RSTR 272
#define KROWS (128*RSTR)               // 34816: 128 rows (K or V)
#define KVBUF (2*KROWS)                // 69632: [KH(128r) | VH(128r)]
#define NSTG  3
#define SMEM_ATTN (NSTG*KVBUF)         // 208896

// ---------------- prep: rotate + fp16 convert, 2 rows/warp, batched loads ----------------
__global__ __launch_bounds__(256) void prep_qkv(const float* __restrict__ Q,
                                                const float* __restrict__ K,
                                                const float* __restrict__ V,
                                                float* __restrict__ ratio) {
    if (blockIdx.x == 0 && blockIdx.y == 0 && threadIdx.x < 4) ratio[threadIdx.x] = 0.f;
    const int h = blockIdx.y;
    const int warp = threadIdx.x >> 5, lane = threadIdx.x & 31;
    const int s0 = blockIdx.x * 16 + warp * 2;      // 601*16 = 9616 exact

    const int g0 = orig_idx(s0), g1 = orig_idx(s0 + 1);
    const size_t si0 = ((size_t)g0 * NH + h) * HD + lane * 4;
    const size_t si1 = ((size_t)g1 * NH + h) * HD + lane * 4;

    // issue all 6 loads back-to-back (MLP 6)
    float4 q0 = *(const float4*)(Q + si0);
    float4 q1 = *(const float4*)(Q + si1);
    float4 k0 = *(const float4*)(K + si0);
    float4 k1 = *(const float4*)(K + si1);
    float4 v0 = *(const float4*)(V + si0);
    float4 v1 = *(const float4*)(V + si1);

    const size_t o0 = ((size_t)h * S_TOT + s0)     * HD + lane * 4;
    const size_t o1 = ((size_t)h * S_TOT + s0 + 1) * HD + lane * 4;
    *(uint2*)(g_Qh + o0) = make_uint2(pack2(q0.x * QSCALE, q0.y * QSCALE),
                                      pack2(q0.z * QSCALE, q0.w * QSCALE));
    *(uint2*)(g_Qh + o1) = make_uint2(pack2(q1.x * QSCALE, q1.y * QSCALE),
                                      pack2(q1.z * QSCALE, q1.w * QSCALE));
    *(uint2*)(g_Kh + o0) = make_uint2(pack2(k0.x, k0.y), pack2(k0.z, k0.w));
    *(uint2*)(g_Kh + o1) = make_uint2(pack2(k1.x, k1.y), pack2(k1.z, k1.w));
    *(uint2*)(g_Vh + o0) = make_uint2(pack2(v0.x, v0.y), pack2(v0.z, v0.w));
    *(uint2*)(g_Vh + o1) = make_uint2(pack2(v1.x, v1.y), pack2(v1.z, v1.w));
}

// ---------------- async KV block load: 128 rows of K and V ----------------
__device__ __forceinline__ void kv_load(u32 kvb, int c0, int tid,
    const __half* kh, const __half* vh)
{
#pragma unroll
    for (int it = 0; it < 8; it++) {
        int idx = tid + it * 256;            // 0..2047
        int row = idx >> 4, ch = idx & 15;
        size_t src = (size_t)min(c0 + row, S_TOT - 1) * HD + ch * 8;
        u32 dst = kvb + row * RSTR + ch * 16;
        CP_ASYNC16(dst,         kh + src);
        CP_ASYNC16(dst + KROWS, vh + src);
    }
}

// ---------------- fused attention + ratio kernel (frozen R12 structure) ----------------
__global__ __launch_bounds__(256, 1)
void fused_kernel(float* __restrict__ O, float* __restrict__ ratio)
{
    extern __shared__ char sm[];
    const u32 sb  = smem_u32(sm);
    const int tid = threadIdx.x, w = tid >> 5, lane = tid & 31;
    const int g = lane >> 2, tg = lane & 3;

    if (blockIdx.x >= 306) {
        // ================= ratio path (fp16 QK, Q frags in registers) =================
        int e = blockIdx.x - 306;            // 0..35
        const int type = e / 18, head = (e / 9) & 1, rb = e % 9;
        const int r0 = rb * 128;
        const int stride = type ? 8 : 1;

        const __half* qh = g_Qh + (size_t)head * S_TOT * HD;
        const __half* kh = g_Kh + (size_t)head * S_TOT * HD;

        // Q fragments direct from global (A-frag layout)
        u32 qf[8][4];
        {
            const int rqa = min(r0 + w * 16 + g,     PF - 1) * stride;
            const int rqb = min(r0 + w * 16 + g + 8, PF - 1) * stride;
#pragma unroll
            for (int kc = 0; kc < 8; kc++) {
                int d = kc * 16 + 2 * tg;
                qf[kc][0] = *(const u32*)(qh + (size_t)rqa * HD + d);
                qf[kc][1] = *(const u32*)(qh + (size_t)rqb * HD + d);
                qf[kc][2] = *(const u32*)(qh + (size_t)rqa * HD + d + 8);
                qf[kc][3] = *(const u32*)(qh + (size_t)rqb * HD + d + 8);
            }
        }

        const u32 bAddr = sb + ((lane & 7) + ((lane >> 4) & 1) * 8) * RSTR
                        + ((lane >> 3) & 1) * 16;

        float totA = 0.f, winA = 0.f, totB = 0.f, winB = 0.f;
        const int rA = r0 + w * 16 + g, rB = rA + 8;

        for (int blk = 0; blk < 17; blk++) {
            const int c0 = blk * 64;
            __syncthreads();
#pragma unroll
            for (int it = 0; it < 4; it++) {
                int idx = tid + it * 256;
                int row = idx >> 4, ch = idx & 15;
                size_t src = (size_t)(min(c0 + row, PF - 1) * stride) * HD + ch * 8;
                *(uint4*)(sm + row * RSTR + ch * 16) = *(const uint4*)(kh + src);
            }
            __syncthreads();

            float s[8][4];
#pragma unroll
            for (int x = 0; x < 8; x++)
#pragma unroll
                for (int j = 0; j < 4; j++) s[x][j] = 0.f;
#pragma unroll
            for (int kc = 0; kc < 8; kc++) {
#pragma unroll
                for (int nb2 = 0; nb2 < 4; nb2++) {
                    u32 Bh[4];
                    ldsm4(Bh, bAddr + nb2 * (16 * RSTR) + kc * 32);
                    mma(s[2*nb2],   qf[kc], Bh[0], Bh[1]);
                    mma(s[2*nb2+1], qf[kc], Bh[2], Bh[3]);
                }
            }
#pragma unroll
            for (int nb = 0; nb < 8; nb++) {
                int c = c0 + nb * 8 + 2 * tg;
#pragma unroll
                for (int v = 0; v < 4; v++) {
                    int cc = c + (v & 1);
                    int rr = (v < 2) ? rA : rB;
                    float p = (cc < PF) ? ex2(s[nb][v]) : 0.f;
                    if (v < 2) { totA += p; if (abs(rr - cc) <= WIN) winA += p; }
                    else       { totB += p; if (abs(rr - cc) <= WIN) winB += p; }
                }
            }
        }

        totA += __shfl_xor_sync(0xffffffffu, totA, 1);
        totA += __shfl_xor_sync(0xffffffffu, totA, 2);
        winA += __shfl_xor_sync(0xffffffffu, winA, 1);
        winA += __shfl_xor_sync(0xffffffffu, winA, 2);
        totB += __shfl_xor_sync(0xffffffffu, totB, 1);
        totB += __shfl_xor_sync(0xffffffffu, totB, 2);
        winB += __shfl_xor_sync(0xffffffffu, winB, 1);
        winB += __shfl_xor_sync(0xffffffffu, winB, 2);

        float* red = (float*)sm;
        __syncthreads();
        if (tid == 0) red[0] = 0.f;
        __syncthreads();
        if (tg == 0) {
            float contrib = 0.f;
            if (rA < PF) contrib += winA / totA;
            if (rB < PF) contrib += winB / totB;
            if (contrib != 0.f) atomicAdd(red, contrib);
        }
        __syncthreads();
        if (tid == 0) atomicAdd(&ratio[type * NH + head], red[0] * (1.f / (float)PF));
        return;
    }

    // ================= attention path (128-col big-iters, 3-stage pipeline) =================
    int tile, head, chunk = -1, eidx = 0;
    int lo0, hi0, lo1, hi1;
    if (blockIdx.x < 130) {
        tile = blockIdx.x >> 1; head = blockIdx.x & 1;
        lo0 = max(0, tile - 16); hi0 = min(64, tile + 16);   // band, 128-blocks
        lo1 = 65; hi1 = 75;                                   // tail
    } else {
        int e = blockIdx.x - 130;
        int tileIdx = e >> 4; head = (e >> 3) & 1; chunk = e & 7;
        tile = 65 + tileIdx;
        eidx = e;
        lo0 = (76 * chunk) / 8; hi0 = (76 * (chunk + 1)) / 8 - 1;
        lo1 = 0; hi1 = -1;
    }
    const int r0 = tile * 128;
    const bool rowRazor = (tile < 65);
    const int n0 = hi0 - lo0 + 1;
    const int nb_total = n0 + (hi1 >= lo1 ? hi1 - lo1 + 1 : 0);

    const __half* qh = g_Qh + (size_t)head * S_TOT * HD;
    const __half* kh = g_Kh + (size_t)head * S_TOT * HD;
    const __half* vh = g_Vh + (size_t)head * S_TOT * HD;

#define BLK_OF(j) (((j) < n0) ? lo0 + (j) : lo1 + ((j) - n0))

    // prologue: issue loads for big-iters 0 and 1
    kv_load(sb,         BLK_OF(0) * 128, tid, kh, vh);
    CP_COMMIT();
    kv_load(sb + KVBUF, BLK_OF(min(1, nb_total - 1)) * 128, tid, kh, vh);
    CP_COMMIT();

    // Q fragments direct from global (A-frag layout), held for entire kernel
    u32 qf[8][4];
    {
        const int rqa = min(r0 + w * 16 + g,     S_TOT - 1);
        const int rqb = min(r0 + w * 16 + g + 8, S_TOT - 1);
#pragma unroll
        for (int kc = 0; kc < 8; kc++) {
            int d = kc * 16 + 2 * tg;
            qf[kc][0] = *(const u32*)(qh + (size_t)rqa * HD + d);
            qf[kc][1] = *(const u32*)(qh + (size_t)rqb * HD + d);
            qf[kc][2] = *(const u32*)(qh + (size_t)rqa * HD + d + 8);
            qf[kc][3] = *(const u32*)(qh + (size_t)rqb * HD + d + 8);
        }
    }

    const u32 offBK = ((lane & 7) + ((lane >> 4) & 1) * 8) * RSTR + ((lane >> 3) & 1) * 16;
    const u32 offBV = KROWS + ((lane & 7) + ((lane >> 3) & 1) * 8) * RSTR + ((lane >> 4) & 1) * 16;

    float o[16][4];
#pragma unroll
    for (int i = 0; i < 16; i++)
#pragma unroll
        for (int j = 0; j < 4; j++) o[i][j] = 0.f;
    float laccF[4] = {0.f, 0.f, 0.f, 0.f};      // row sums via ones-MMA
    const int rA = r0 + w * 16 + g, rB = rA + 8;
    const int t2lo = 2 * tile - 30, t2hi = 2 * tile + 31;

    int st = 0;                                   // stage being consumed
    for (int i = 0; i < nb_total; i++) {
        const int blk = BLK_OF(i);

        CP_WAIT1();            // iter i's group complete (<=1 outstanding)
        __syncthreads();       // CTA-wide visibility; all warps past iter i-1
        {
            int nxt = i + 2;
            if (nxt < nb_total) {
                int ns = st + 2; if (ns >= NSTG) ns -= NSTG;   // stage freed at i-1
                kv_load(sb + ns * KVBUF, BLK_OF(nxt) * 128, tid, kh, vh);
            }
            CP_COMMIT();       // uniform group counting
        }
        const u32 kvb = sb + st * KVBUF;
        if (++st == NSTG) st = 0;

#pragma unroll
        for (int h = 0; h < 2; h++) {
            const int sub = 2 * blk + h;          // 64-col sub-block index
            if (sub == 151) continue;             // beyond sequence entirely
            const int c0 = sub * 64;
            int maskMode = 0;
            if (sub < 130) { if (rowRazor && (sub < t2lo || sub > t2hi)) maskMode = 1; }
            else if (sub == 150) maskMode = 2;
            const u32 hof = h * (64 * RSTR);

            // ---- QK: S = Qh * Kh ----
            float s[8][4];
#pragma unroll
            for (int x = 0; x < 8; x++)
#pragma unroll
                for (int j = 0; j < 4; j++) s[x][j] = 0.f;

#pragma unroll
            for (int kc = 0; kc < 8; kc++) {
#pragma unroll
                for (int nb2 = 0; nb2 < 4; nb2++) {
                    u32 Bh[4];
                    ldsm4(Bh, kvb + offBK + hof + nb2 * (16 * RSTR) + kc * 32);
                    mma(s[2*nb2],   qf[kc], Bh[0], Bh[1]);
                    mma(s[2*nb2+1], qf[kc], Bh[2], Bh[3]);
                }
            }

            // ---- epilogue: mask + ex2 + fp16 pack ----
            u32 ph[8][2];
#pragma unroll
            for (int nb = 0; nb < 8; nb++) {
                int c = c0 + nb * 8 + 2 * tg;
                float p00 = ex2(s[nb][0]);
                float p01 = ex2(s[nb][1]);
                float p10 = ex2(s[nb][2]);
                float p11 = ex2(s[nb][3]);
                if (maskMode == 1) {
                    if ((unsigned)(c     - (rA - PRE)) > 2u*PRE) p00 = 0.f;
                    if ((unsigned)(c + 1 - (rA - PRE)) > 2u*PRE) p01 = 0.f;
                    if ((unsigned)(c     - (rB - PRE)) > 2u*PRE) p10 = 0.f;
                    if ((unsigned)(c + 1 - (rB - PRE)) > 2u*PRE) p11 = 0.f;
                } else if (maskMode == 2) {
                    if (c     >= S_TOT) { p00 = 0.f; p10 = 0.f; }
                    if (c + 1 >= S_TOT) { p01 = 0.f; p11 = 0.f; }
                }
                ph[nb][0] = pack2(p00, p01);
                ph[nb][1] = pack2(p10, p11);
            }

            // ---- PV: O += P * Vh ; lacc += P * ones ----
#pragma unroll
            for (int kc = 0; kc < 4; kc++) {
                u32 Ah[4] = { ph[2*kc][0], ph[2*kc][1], ph[2*kc+1][0], ph[2*kc+1][1] };
                mma(laccF, Ah, ONES16, ONES16);     // row sums (free l accumulation)
#pragma unroll
                for (int nb2 = 0; nb2 < 8; nb2++) {
                    u32 Bh[4];
                    ldsm4t(Bh, kvb + offBV + hof + kc * (16 * RSTR) + nb2 * 32);
                    mma(o[2*nb2],   Ah, Bh[0], Bh[1]);
                    mma(o[2*nb2+1], Ah, Bh[2], Bh[3]);
                }
            }
        }
    }

    // ---- finalize (laccF[0]/[2] are complete row sums) ----
    const float laccA = laccF[0], laccB = laccF[2];

    if (chunk < 0) {
        float invA = 1.f / laccA, invB = 1.f / laccB;
        if (rA < S_TOT) {
            float* base = O + ((size_t)orig_idx(rA) * NH + head) * HD;
#pragma unroll
            for (int nb = 0; nb < 16; nb++)
                *(float2*)(base + nb * 8 + 2 * tg) = make_float2(o[nb][0] * invA, o[nb][1] * invA);
        }
        if (rB < S_TOT) {
            float* base = O + ((size_t)orig_idx(rB) * NH + head) * HD;
#pragma unroll
            for (int nb = 0; nb < 16; nb++)
                *(float2*)(base + nb * 8 + 2 * tg) = make_float2(o[nb][2] * invB, o[nb][3] * invB);
        }
    } else {
        float* so = g_scrO + (size_t)eidx * 16384;
        int rlA = w * 16 + g, rlB = rlA + 8;
#pragma unroll
        for (int nb = 0; nb < 16; nb++) {
            *(float2*)(so + rlA * 128 + nb * 8 + 2 * tg) = make_float2(o[nb][0], o[nb][1]);
            *(float2*)(so + rlB * 128 + nb * 8 + 2 * tg) = make_float2(o[nb][2], o[nb][3]);
        }
        if (tg == 0) {
            g_scrL[eidx * 128 + rlA] = laccA;
            g_scrL[eidx * 128 + rlB] = laccB;
        }
    }
}

// ---------------- combine tail partials (wide grid, float4) ----------------
__global__ __launch_bounds__(256) void combine_kernel(float* __restrict__ O) {
    int pair  = blockIdx.x >> 4;
    int slice = blockIdx.x & 15;
    int tileIdx = pair >> 1, head = pair & 1;
    int tile = 65 + tileIdx, r0 = tile * 128;
    int ebase = tileIdx * 16 + head * 8;
    int tid = threadIdx.x;

    __shared__ float ls[8];
    if (tid < 8) {
        int row = slice * 8 + tid;
        float sum = 0.f;
#pragma unroll
        for (int c = 0; c < NCHUNK; c++) sum += g_scrL[(ebase + c) * 128 + row];
        ls[tid] = 1.f / sum;
    }
    __syncthreads();

    int k = slice * 1024 + tid * 4;           // float4-aligned element index
    int row = k >> 7, col = k & 127;
    if (r0 + row >= S_TOT) return;
    float4 acc = make_float4(0.f, 0.f, 0.f, 0.f);
#pragma unroll
    for (int c = 0; c < NCHUNK; c++) {
        float4 v = *(const float4*)(g_scrO + (size_t)(ebase + c) * 16384 + k);
        acc.x += v.x; acc.y += v.y; acc.z += v.z; acc.w += v.w;
    }
    float inv = ls[row - slice * 8];
    int gr = orig_idx(r0 + row);
    acc.x *= inv; acc.y *= inv; acc.z *= inv; acc.w *= inv;
    *(float4*)(O + ((size_t)gr * NH + head) * HD + col) = acc;
}

// ---------------- launch ----------------
extern "C" void kernel_launch(void* const* d_in, const int* in_sizes, int n_in,
                              void* d_out, int out_size)
{
    const float* Q = (const float*)d_in[0];
    const float* K = (const float*)d_in[1];
    const float* V = (const float*)d_in[2];
    float* O     = (float*)d_out;
    float* ratio = O + (size_t)S_TOT * NH * HD;

    cudaFuncSetAttribute(fused_kernel, cudaFuncAttributeMaxDynamicSharedMemorySize, SMEM_ATTN);

    prep_qkv<<<dim3(601, NH), 256>>>(Q, K, V, ratio);
    fused_kernel<<<342, 256, SMEM_ATTN>>>(O, ratio);
    combine_kernel<<<352, 256>>>(O);
}